// round 1
// baseline (speedup 1.0000x reference)
#include <cuda_runtime.h>

#define HH 128
#define WW 128
#define NPIX (HH*WW)
#define NB 16
#define NTHREADS 512

// Scratch (no allocations allowed) ------------------------------------------
__device__ float g_S[NPIX];        // 2D prefix sum of template
__device__ float g_W[NPIX];        // effective per-pixel template weight
__device__ float g_sample[NB];     // per-sample loss

// ---------------------------------------------------------------------------
// Kernel 1: build W[y][x] = sum of T over window [y-64,y+63]x[x-64,x+63] clipped
// via 2D inclusive prefix sums. One block, 128 threads.
// ---------------------------------------------------------------------------
__global__ void prep_weight_kernel(const float* __restrict__ T) {
    int t = threadIdx.x;  // 0..127

    // row-wise inclusive prefix (thread t owns row t)
    float acc = 0.0f;
    #pragma unroll 4
    for (int x = 0; x < WW; ++x) { acc += T[t * WW + x]; g_S[t * WW + x] = acc; }
    __syncthreads();

    // column-wise inclusive prefix (thread t owns column t)
    acc = 0.0f;
    #pragma unroll 4
    for (int y = 0; y < HH; ++y) { acc += g_S[y * WW + t]; g_S[y * WW + t] = acc; }
    __syncthreads();

    // W row y = t
    int y = t;
    int y0 = max(0, y - 64), y1 = min(HH - 1, y + 63);
    float top = (y0 > 0) ? 0.0f : 0.0f;  // handled per-corner below
    (void)top;
    for (int x = 0; x < WW; ++x) {
        int x0 = max(0, x - 64), x1 = min(WW - 1, x + 63);
        float s11 = g_S[y1 * WW + x1];
        float s01 = (y0 > 0) ? g_S[(y0 - 1) * WW + x1] : 0.0f;
        float s10 = (x0 > 0) ? g_S[y1 * WW + (x0 - 1)] : 0.0f;
        float s00 = (y0 > 0 && x0 > 0) ? g_S[(y0 - 1) * WW + (x0 - 1)] : 0.0f;
        g_W[y * WW + x] = s11 - s01 - s10 + s00;
    }
}

// ---------------------------------------------------------------------------
// Kernel 2: per-sample loss. One block per batch image, 512 threads.
//  - mask bits in shared (2KB), labels uint16 in shared (32KB)
//  - area / perimeter (Sobel-nonzero) / template weighted sum / CCL count
// ---------------------------------------------------------------------------
#define GETBIT(idx) ((mbits[(idx) >> 5] >> ((idx) & 31)) & 1u)

__global__ __launch_bounds__(NTHREADS) void per_sample_kernel(const float* __restrict__ preds) {
    __shared__ unsigned       mbits[NPIX / 32];     // 512 words = 2 KB
    __shared__ unsigned short lab[NPIX];            // 32 KB
    __shared__ int            s_changed;
    __shared__ int            s_area[16], s_perim[16], s_ncomp[16];
    __shared__ double         s_wsum[16];

    const int b    = blockIdx.x;
    const float* p = preds + (size_t)b * NPIX;
    const int tid  = threadIdx.x;
    const int lane = tid & 31;
    const int warp = tid >> 5;                      // 16 warps

    // ---- build binary mask bits (coalesced, ballot per 32 pixels) ----
    for (int w = warp; w < NPIX / 32; w += 16) {
        float v = p[w * 32 + lane];
        unsigned word = __ballot_sync(0xFFFFFFFFu, v > 0.5f);
        if (lane == 0) mbits[w] = word;
    }
    __syncthreads();

    // ---- area, perimeter, template weighted sum, label init ----
    int    area  = 0;
    int    perim = 0;
    double wsum  = 0.0;
    for (int i = tid; i < NPIX; i += NTHREADS) {
        int y = i >> 7, x = i & 127;
        int c = GETBIT(i);
        area += c;
        if (c) wsum += (double)g_W[i];
        lab[i] = c ? (unsigned short)i : (unsigned short)0xFFFF;

        // 3x3 neighborhood with zero padding (SAME)
        int b00 = (y > 0   && x > 0  ) ? GETBIT(i - 129) : 0;
        int b01 = (y > 0             ) ? GETBIT(i - 128) : 0;
        int b02 = (y > 0   && x < 127) ? GETBIT(i - 127) : 0;
        int b10 = (            x > 0 ) ? GETBIT(i - 1)   : 0;
        int b12 = (            x < 127)? GETBIT(i + 1)   : 0;
        int b20 = (y < 127 && x > 0  ) ? GETBIT(i + 127) : 0;
        int b21 = (y < 127           ) ? GETBIT(i + 128) : 0;
        int b22 = (y < 127 && x < 127) ? GETBIT(i + 129) : 0;
        int gx = (b02 + 2 * b12 + b22) - (b00 + 2 * b10 + b20);
        int gy = (b20 + 2 * b21 + b22) - (b00 + 2 * b01 + b02);
        perim += ((gx | gy) != 0);
    }
    __syncthreads();

    // ---- connected components: min-label propagation + pointer jumping ----
    // Labels only decrease; races are benign (any observed value is a valid
    // in-component label). Terminate on a fully-synchronized stable pass,
    // which yields the exact per-component min-index fixed point (== reference).
    for (;;) {
        if (tid == 0) s_changed = 0;
        __syncthreads();
        bool any = false;
        for (int i = tid; i < NPIX; i += NTHREADS) {
            if (!GETBIT(i)) continue;
            int y = i >> 7, x = i & 127;
            unsigned short l = lab[i];
            unsigned short m = l;
            if (y > 0   && GETBIT(i - 128)) { unsigned short v = lab[i - 128]; if (v < m) m = v; }
            if (y < 127 && GETBIT(i + 128)) { unsigned short v = lab[i + 128]; if (v < m) m = v; }
            if (x > 0   && GETBIT(i - 1))   { unsigned short v = lab[i - 1];   if (v < m) m = v; }
            if (x < 127 && GETBIT(i + 1))   { unsigned short v = lab[i + 1];   if (v < m) m = v; }
            // pointer jump (m always indexes a mask pixel of the same component)
            unsigned short lm = lab[m]; if (lm < m) m = lm;
            lm = lab[m]; if (lm < m) m = lm;
            if (m < l) { lab[i] = m; any = true; }
        }
        if (any) s_changed = 1;   // benign race: all writers write 1
        __syncthreads();
        if (!s_changed) break;
    }

    // ---- component count: roots are pixels with lab == own index ----
    int ncomp = 0;
    for (int i = tid; i < NPIX; i += NTHREADS)
        if (GETBIT(i) && lab[i] == (unsigned short)i) ncomp++;

    // ---- block reductions (warp shuffle, then 16 partials) ----
    #pragma unroll
    for (int o = 16; o > 0; o >>= 1) {
        area  += __shfl_down_sync(0xFFFFFFFFu, area,  o);
        perim += __shfl_down_sync(0xFFFFFFFFu, perim, o);
        ncomp += __shfl_down_sync(0xFFFFFFFFu, ncomp, o);
        wsum  += __shfl_down_sync(0xFFFFFFFFu, wsum,  o);
    }
    if (lane == 0) {
        s_area[warp]  = area;
        s_perim[warp] = perim;
        s_ncomp[warp] = ncomp;
        s_wsum[warp]  = wsum;
    }
    __syncthreads();

    if (tid == 0) {
        int    A = 0, P = 0, C = 0;
        double WS = 0.0;
        #pragma unroll
        for (int w = 0; w < 16; ++w) { A += s_area[w]; P += s_perim[w]; C += s_ncomp[w]; WS += s_wsum[w]; }

        float fa = (float)A;
        float fp = (float)P;
        float compact  = (fp * fp) / (fa + 1e-6f);
        float geometry = (A == 0) ? 0.0f : fabsf(compact - 4.51f);
        float multi    = (float)max(C - 1, 0);
        float tmpl     = 1.0f - (float)(WS / 16384.0);
        g_sample[b] = multi + geometry + tmpl;
    }
}

// ---------------------------------------------------------------------------
// Kernel 3: deterministic final reduction, write scalar output.
// ---------------------------------------------------------------------------
__global__ void finalize_kernel(float* __restrict__ out, int out_size) {
    double s = 0.0;
    #pragma unroll
    for (int i = 0; i < NB; ++i) s += (double)g_sample[i];
    float v = (float)(s / (double)NB);   // WEIGHT = 1.0
    for (int i = 0; i < out_size; ++i) out[i] = v;
}

// ---------------------------------------------------------------------------
extern "C" void kernel_launch(void* const* d_in, const int* in_sizes, int n_in,
                              void* d_out, int out_size) {
    const float* preds = (const float*)d_in[0];     // [16,1,128,128]
    const float* templ = (const float*)d_in[1];     // [1,1,128,128]
    (void)in_sizes; (void)n_in;

    prep_weight_kernel<<<1, 128>>>(templ);
    per_sample_kernel<<<NB, NTHREADS>>>(preds);
    finalize_kernel<<<1, 1>>>((float*)d_out, out_size);
}

// round 4
// speedup vs baseline: 4.4756x; 4.4756x over previous
#include <cuda_runtime.h>

#define HH 128
#define WW 128
#define NPIX (HH*WW)
#define NB 16
#define NTHREADS 512
#define PITCH 129   // padded row pitch for the shared integral image (kills column bank conflicts)

// Persistent device scratch (no allocations allowed)
__device__ float g_sample[NB];
__device__ int   g_done = 0;     // last-block ticket; reset to 0 by last block each launch

#define GETBIT(idx) ((mbits[(idx) >> 5] >> ((idx) & 31)) & 1u)

// ---- lock-free union-find (shared memory, atomicMin union => root = component min index) ----
__device__ __forceinline__ int find_root(volatile int* lab, int a) {
    int p = lab[a];
    while (p != a) { a = p; p = lab[a]; }
    return a;
}
__device__ __forceinline__ void merge_px(int* lab, int a, int b) {
    for (;;) {
        a = find_root(lab, a);
        b = find_root(lab, b);
        if (a == b) return;
        int mn = min(a, b), mx = max(a, b);
        int old = atomicMin(&lab[mx], mn);
        if (old == mx) return;   // successfully attached mx under mn
        a = mn; b = old;         // someone raced us; retry with their root
    }
}

extern __shared__ char smem_raw[];

__global__ __launch_bounds__(NTHREADS)
void fused_hexloss_kernel(const float* __restrict__ preds,
                          const float* __restrict__ templ,
                          float* __restrict__ out, int out_size)
{
    // dynamic shared: first used as padded float integral image (128x129 = 66048 B),
    // then reused as int labels (16384 x 4 = 65536 B)
    float* sS  = reinterpret_cast<float*>(smem_raw);
    int*   lab = reinterpret_cast<int*>(smem_raw);

    __shared__ unsigned mbits[NPIX / 32];         // 2 KB binary mask
    __shared__ int      s_area[16], s_perim[16], s_ncomp[16];
    __shared__ double   s_wsum[16];

    const int b    = blockIdx.x;
    const int tid  = threadIdx.x;
    const int lane = tid & 31;
    const int warp = tid >> 5;                    // 16 warps
    const unsigned FULL = 0xFFFFFFFFu;
    const float* p = preds + (size_t)b * NPIX;

    // ---- load template into padded shared + build mask bits (independent streams) ----
    for (int i = tid; i < NPIX; i += NTHREADS)
        sS[(i >> 7) * PITCH + (i & 127)] = templ[i];
    for (int w = warp; w < NPIX / 32; w += 16) {
        float v = p[w * 32 + lane];
        unsigned word = __ballot_sync(FULL, v > 0.5f);
        if (lane == 0) mbits[w] = word;
    }
    __syncthreads();

    // ---- row-wise inclusive scan (warp per row, shuffle scan, 4 segments of 32) ----
    for (int r = warp; r < HH; r += 16) {
        float carry = 0.0f;
        #pragma unroll
        for (int seg = 0; seg < 4; ++seg) {
            float v = sS[r * PITCH + seg * 32 + lane];
            #pragma unroll
            for (int o = 1; o < 32; o <<= 1) {
                float t = __shfl_up_sync(FULL, v, o);
                if (lane >= o) v += t;
            }
            v += carry;
            sS[r * PITCH + seg * 32 + lane] = v;
            carry = __shfl_sync(FULL, v, 31);
        }
    }
    __syncthreads();

    // ---- column-wise inclusive scan (warp per column; PITCH=129 => conflict-free) ----
    for (int c = warp; c < WW; c += 16) {
        float carry = 0.0f;
        #pragma unroll
        for (int seg = 0; seg < 4; ++seg) {
            float v = sS[(seg * 32 + lane) * PITCH + c];
            #pragma unroll
            for (int o = 1; o < 32; o <<= 1) {
                float t = __shfl_up_sync(FULL, v, o);
                if (lane >= o) v += t;
            }
            v += carry;
            sS[(seg * 32 + lane) * PITCH + c] = v;
            carry = __shfl_sync(FULL, v, 31);
        }
    }
    __syncthreads();

    // ---- area / perimeter (Sobel-nonzero) / template weighted sum ----
    int    area  = 0;
    int    perim = 0;
    double wsum  = 0.0;
    for (int i = tid; i < NPIX; i += NTHREADS) {
        int y = i >> 7, x = i & 127;
        int c = GETBIT(i);
        area += c;
        if (c) {
            // W[y][x] = sum of template over window [y-64,y+63]x[x-64,x+63] clipped
            int y0 = max(0, y - 64), y1 = min(HH - 1, y + 63);
            int x0 = max(0, x - 64), x1 = min(WW - 1, x + 63);
            float s11 = sS[y1 * PITCH + x1];
            float s01 = (y0 > 0) ? sS[(y0 - 1) * PITCH + x1] : 0.0f;
            float s10 = (x0 > 0) ? sS[y1 * PITCH + (x0 - 1)] : 0.0f;
            float s00 = (y0 > 0 && x0 > 0) ? sS[(y0 - 1) * PITCH + (x0 - 1)] : 0.0f;
            wsum += (double)(s11 - s01 - s10 + s00);
        }
        // Sobel with SAME zero padding; edge iff gx or gy nonzero
        int b00 = (y > 0   && x > 0  ) ? GETBIT(i - 129) : 0;
        int b01 = (y > 0             ) ? GETBIT(i - 128) : 0;
        int b02 = (y > 0   && x < 127) ? GETBIT(i - 127) : 0;
        int b10 = (            x > 0 ) ? GETBIT(i - 1)   : 0;
        int b12 = (            x < 127)? GETBIT(i + 1)   : 0;
        int b20 = (y < 127 && x > 0  ) ? GETBIT(i + 127) : 0;
        int b21 = (y < 127           ) ? GETBIT(i + 128) : 0;
        int b22 = (y < 127 && x < 127) ? GETBIT(i + 129) : 0;
        int gx = (b02 + 2 * b12 + b22) - (b00 + 2 * b10 + b20);
        int gy = (b20 + 2 * b21 + b22) - (b00 + 2 * b01 + b02);
        perim += ((gx | gy) != 0);
    }
    __syncthreads();   // all reads of sS done before label reuse

    // ---- connected components via union-find (single merge pass) ----
    for (int i = tid; i < NPIX; i += NTHREADS) lab[i] = i;
    __syncthreads();
    for (int i = tid; i < NPIX; i += NTHREADS) {
        if (!GETBIT(i)) continue;
        int y = i >> 7, x = i & 127;
        if (x < 127 && GETBIT(i + 1))   merge_px(lab, i, i + 1);
        if (y < 127 && GETBIT(i + 128)) merge_px(lab, i, i + 128);
    }
    __syncthreads();

    // component count = number of roots among mask pixels
    int ncomp = 0;
    for (int i = tid; i < NPIX; i += NTHREADS)
        if (GETBIT(i) && lab[i] == i) ncomp++;

    // ---- block reduction ----
    #pragma unroll
    for (int o = 16; o > 0; o >>= 1) {
        area  += __shfl_down_sync(FULL, area,  o);
        perim += __shfl_down_sync(FULL, perim, o);
        ncomp += __shfl_down_sync(FULL, ncomp, o);
        wsum  += __shfl_down_sync(FULL, wsum,  o);
    }
    if (lane == 0) { s_area[warp] = area; s_perim[warp] = perim; s_ncomp[warp] = ncomp; s_wsum[warp] = wsum; }
    __syncthreads();

    if (tid == 0) {
        int A = 0, P = 0, C = 0; double WS = 0.0;
        #pragma unroll
        for (int w = 0; w < 16; ++w) { A += s_area[w]; P += s_perim[w]; C += s_ncomp[w]; WS += s_wsum[w]; }

        float fa = (float)A, fp = (float)P;
        float compact  = (fp * fp) / (fa + 1e-6f);
        float geometry = (A == 0) ? 0.0f : fabsf(compact - 4.51f);
        float multi    = (float)max(C - 1, 0);
        float tmpl     = 1.0f - (float)(WS / 16384.0);
        g_sample[b] = multi + geometry + tmpl;

        // last-block finalize (deterministic: fixed-order sum over 16 slots)
        __threadfence();
        int ticket = atomicAdd(&g_done, 1);
        if (ticket == NB - 1) {
            double s = 0.0;
            #pragma unroll
            for (int i = 0; i < NB; ++i) s += (double)g_sample[i];
            float v = (float)(s / (double)NB);   // WEIGHT = 1.0
            for (int i = 0; i < out_size; ++i) out[i] = v;
            g_done = 0;   // self-reset for next replay
        }
    }
}

// ---------------------------------------------------------------------------
extern "C" void kernel_launch(void* const* d_in, const int* in_sizes, int n_in,
                              void* d_out, int out_size) {
    const float* preds = (const float*)d_in[0];   // [16,1,128,128]
    const float* templ = (const float*)d_in[1];   // [1,1,128,128]
    (void)in_sizes; (void)n_in;

    const int smem_bytes = HH * PITCH * (int)sizeof(float);   // 66048 B (>= 65536 label bytes)
    static bool attr_set = false;
    // setting a func attribute is idempotent & not a stream op; safe under capture
    cudaFuncSetAttribute(fused_hexloss_kernel,
                         cudaFuncAttributeMaxDynamicSharedMemorySize, smem_bytes);
    (void)attr_set;

    fused_hexloss_kernel<<<NB, NTHREADS, smem_bytes>>>(preds, templ, (float*)d_out, out_size);
}

// round 6
// speedup vs baseline: 20.1646x; 4.5054x over previous
#include <cuda_runtime.h>

#define HH 128
#define WW 128
#define NPIX (HH*WW)
#define NWORDS (NPIX/32)   // 512
#define NB 16
#define NTHREADS 512
#define PITCH 129          // padded pitch for shared integral image

__device__ float g_sample[NB];
__device__ int   g_done = 0;   // self-resetting last-block ticket

// ---- lock-free union-find with atomicMin path-halving (monotone => race-safe) ----
__device__ __forceinline__ int find_root(int* lab, int a) {
    for (;;) {
        int p = lab[a];
        if (p == a) return a;
        int gp = lab[p];
        if (gp == p) return p;
        atomicMin(&lab[a], gp);   // path halving; only ever lowers, never breaks links
        a = gp;
    }
}
__device__ __forceinline__ void merge_px(int* lab, int a, int b) {
    for (;;) {
        a = find_root(lab, a);
        b = find_root(lab, b);
        if (a == b) return;
        int mn = min(a, b), mx = max(a, b);
        int old = atomicMin(&lab[mx], mn);
        if (old == mx) return;
        a = mn; b = old;
    }
}

// bit-sliced 1*p + 2*q + 1*r sum of three 32-lane bit vectors -> 3-bit lanes
#define SUM121(pp,qq,rr,s0,s1,s2) do { unsigned _c = (pp) & (rr); \
    s0 = (pp) ^ (rr); s1 = _c ^ (qq); s2 = _c & (qq); } while (0)

extern __shared__ char smem_raw[];

__global__ __launch_bounds__(NTHREADS)
void fused_hexloss_kernel(const float* __restrict__ preds,
                          const float* __restrict__ templ,
                          float* __restrict__ out, int out_size)
{
    // dynamic smem: phase A = padded float integral image (128x129 = 66048 B)
    //               phase B = int labels (64 KB), reused after integral reads finish
    float* sS  = reinterpret_cast<float*>(smem_raw);
    int*   lab = reinterpret_cast<int*>(smem_raw);

    __shared__ unsigned mbits[NWORDS];     // 2 KB binary mask
    __shared__ int      s_last[NWORDS];    // last run-start position per (row,word), or -1
    __shared__ int      s_area[16], s_perim[16], s_ncomp[16];
    __shared__ double   s_wsum[16];

    const int b    = blockIdx.x;
    const int tid  = threadIdx.x;
    const int lane = tid & 31;
    const int warp = tid >> 5;             // 16 warps
    const unsigned FULL = 0xFFFFFFFFu;
    const float* p = preds + (size_t)b * NPIX;

    // ---- load template to padded shared; build mask bit image ----
    for (int i = tid; i < NPIX; i += NTHREADS)
        sS[(i >> 7) * PITCH + (i & 127)] = templ[i];
    for (int w = warp; w < NWORDS; w += 16) {
        float v = p[w * 32 + lane];
        unsigned word = __ballot_sync(FULL, v > 0.5f);
        if (lane == 0) mbits[w] = word;
    }
    __syncthreads();

    // ---- row-wise inclusive scan (warp per row) ----
    for (int r = warp; r < HH; r += 16) {
        float carry = 0.0f;
        #pragma unroll
        for (int seg = 0; seg < 4; ++seg) {
            float v = sS[r * PITCH + seg * 32 + lane];
            #pragma unroll
            for (int o = 1; o < 32; o <<= 1) {
                float t = __shfl_up_sync(FULL, v, o);
                if (lane >= o) v += t;
            }
            v += carry;
            sS[r * PITCH + seg * 32 + lane] = v;
            carry = __shfl_sync(FULL, v, 31);
        }
    }
    __syncthreads();

    // ---- column-wise inclusive scan (warp per column; PITCH=129 conflict-free) ----
    for (int c = warp; c < WW; c += 16) {
        float carry = 0.0f;
        #pragma unroll
        for (int seg = 0; seg < 4; ++seg) {
            float v = sS[(seg * 32 + lane) * PITCH + c];
            #pragma unroll
            for (int o = 1; o < 32; o <<= 1) {
                float t = __shfl_up_sync(FULL, v, o);
                if (lane >= o) v += t;
            }
            v += carry;
            sS[(seg * 32 + lane) * PITCH + c] = v;
            carry = __shfl_sync(FULL, v, 31);
        }
    }
    __syncthreads();

    // ============= chunk pass: thread <-> (row y, word w), 512 chunks ============
    const int y = tid >> 2;
    const int w = tid & 3;
    const unsigned cur   = mbits[y * 4 + w];
    const unsigned prevw = (w > 0) ? mbits[y * 4 + w - 1] : 0u;
    const unsigned nextw = (w < 3) ? mbits[y * 4 + w + 1] : 0u;

    // 34-bit row windows covering columns [32w-1, 32w+32] (zero pad at image edges)
    unsigned long long Ac = ((unsigned long long)cur << 1) | (prevw >> 31)
                          | ((unsigned long long)(nextw & 1u) << 33);
    unsigned long long Aa = 0ULL, Ab = 0ULL;
    if (y > 0) {
        unsigned c0 = mbits[(y - 1) * 4 + w];
        unsigned p0 = (w > 0) ? mbits[(y - 1) * 4 + w - 1] : 0u;
        unsigned n0 = (w < 3) ? mbits[(y - 1) * 4 + w + 1] : 0u;
        Aa = ((unsigned long long)c0 << 1) | (p0 >> 31) | ((unsigned long long)(n0 & 1u) << 33);
    }
    if (y < 127) {
        unsigned c0 = mbits[(y + 1) * 4 + w];
        unsigned p0 = (w > 0) ? mbits[(y + 1) * 4 + w - 1] : 0u;
        unsigned n0 = (w < 3) ? mbits[(y + 1) * 4 + w + 1] : 0u;
        Ab = ((unsigned long long)c0 << 1) | (p0 >> 31) | ((unsigned long long)(n0 & 1u) << 33);
    }

    // per-column neighbor bit vectors: shift 0 -> col x-1, 1 -> x, 2 -> x+1
    unsigned aL = (unsigned)Aa, aC = (unsigned)(Aa >> 1), aR = (unsigned)(Aa >> 2);
    unsigned cL = (unsigned)Ac,                            cR = (unsigned)(Ac >> 2);
    unsigned bL = (unsigned)Ab, bC = (unsigned)(Ab >> 1), bR = (unsigned)(Ab >> 2);

    // Sobel: edge iff gx!=0 or gy!=0 ; gx = R-L, gy = B-T with 1-2-1 sums (bit-sliced)
    unsigned L0,L1,L2, R0,R1,R2, T0,T1,T2, B0,B1,B2;
    SUM121(aL, cL, bL, L0, L1, L2);
    SUM121(aR, cR, bR, R0, R1, R2);
    SUM121(aL, aC, aR, T0, T1, T2);
    SUM121(bL, bC, bR, B0, B1, B2);
    unsigned eqx = ~((L0 ^ R0) | (L1 ^ R1) | (L2 ^ R2));
    unsigned eqy = ~((T0 ^ B0) | (T1 ^ B1) | (T2 ^ B2));
    int perim = __popc(~(eqx & eqy));
    int area  = __popc(cur);

    // template weighted sum over set pixels (clipped-window integral image reads)
    double wsum = 0.0;
    {
        unsigned m = cur;
        while (m) {
            int j = __ffs(m) - 1; m &= m - 1;
            int x  = w * 32 + j;
            int y1 = min(HH - 1, y + 63);
            int x1 = min(WW - 1, x + 63);
            float s11 = sS[y1 * PITCH + x1];
            float s01 = (y > 64) ? sS[(y - 65) * PITCH + x1] : 0.0f;
            float s10 = (x > 64) ? sS[y1 * PITCH + (x - 65)] : 0.0f;
            float s00 = (y > 64 && x > 64) ? sS[(y - 65) * PITCH + (x - 65)] : 0.0f;
            wsum += (double)(s11 - s01 - s10 + s00);
        }
    }

    // run starts within this word (run = maximal horizontal 1-segment)
    const unsigned starts = cur & ~((cur << 1) | (prevw >> 31));
    s_last[tid] = starts ? (w * 32 + 31 - __clz(starts)) : -1;
    __syncthreads();   // integral reads done -> smem becomes labels; s_last visible

    // ---- init per-pixel labels = run-start index (depth-1 trees) ----
    {
        int carry = -1;
        for (int ww = w - 1; ww >= 0 && carry < 0; --ww) carry = s_last[y * 4 + ww];
        unsigned m = cur;
        const int rowbase = y * 128;
        while (m) {
            int j = __ffs(m) - 1; m &= m - 1;
            unsigned below = (j == 31) ? 0xFFFFFFFFu : ((2u << j) - 1u);
            unsigned sj = starts & below;
            int rs = sj ? (w * 32 + 31 - __clz(sj)) : carry;
            lab[rowbase + w * 32 + j] = rowbase + rs;
        }
    }
    __syncthreads();

    // ---- vertical unions: one merge per overlap SEGMENT between adjacent rows ----
    if (tid < 508) {
        int r  = tid >> 2;
        int ww = tid & 3;
        unsigned ov = mbits[r * 4 + ww] & mbits[(r + 1) * 4 + ww];
        if (ov) {
            unsigned pov = (ww > 0) ? (mbits[r * 4 + ww - 1] & mbits[(r + 1) * 4 + ww - 1]) : 0u;
            unsigned ss = ov & ~((ov << 1) | (pov >> 31));
            while (ss) {
                int j = __ffs(ss) - 1; ss &= ss - 1;
                int x = ww * 32 + j;
                merge_px(lab, lab[r * 128 + x], lab[(r + 1) * 128 + x]);
            }
        }
    }
    __syncthreads();

    // ---- component count: run starts that remained roots ----
    int ncomp = 0;
    {
        unsigned st = starts;
        const int base = y * 128 + w * 32;
        while (st) {
            int j = __ffs(st) - 1; st &= st - 1;
            int i = base + j;
            if (lab[i] == i) ncomp++;
        }
    }

    // ---- block reduction ----
    #pragma unroll
    for (int o = 16; o > 0; o >>= 1) {
        area  += __shfl_down_sync(FULL, area,  o);
        perim += __shfl_down_sync(FULL, perim, o);
        ncomp += __shfl_down_sync(FULL, ncomp, o);
        wsum  += __shfl_down_sync(FULL, wsum,  o);
    }
    if (lane == 0) { s_area[warp] = area; s_perim[warp] = perim; s_ncomp[warp] = ncomp; s_wsum[warp] = wsum; }
    __syncthreads();

    if (tid == 0) {
        int A = 0, P = 0, C = 0; double WS = 0.0;
        #pragma unroll
        for (int ww = 0; ww < 16; ++ww) { A += s_area[ww]; P += s_perim[ww]; C += s_ncomp[ww]; WS += s_wsum[ww]; }

        float fa = (float)A, fp = (float)P;
        float compact  = (fp * fp) / (fa + 1e-6f);
        float geometry = (A == 0) ? 0.0f : fabsf(compact - 4.51f);
        float multi    = (float)max(C - 1, 0);
        float tmpl     = 1.0f - (float)(WS / 16384.0);
        g_sample[b] = multi + geometry + tmpl;

        __threadfence();
        int ticket = atomicAdd(&g_done, 1);
        if (ticket == NB - 1) {
            double s = 0.0;
            #pragma unroll
            for (int i = 0; i < NB; ++i) s += (double)g_sample[i];
            float v = (float)(s / (double)NB);   // WEIGHT = 1.0
            for (int i = 0; i < out_size; ++i) out[i] = v;
            g_done = 0;   // reset for next graph replay
        }
    }
}

// ---------------------------------------------------------------------------
extern "C" void kernel_launch(void* const* d_in, const int* in_sizes, int n_in,
                              void* d_out, int out_size) {
    const float* preds = (const float*)d_in[0];   // [16,1,128,128]
    const float* templ = (const float*)d_in[1];   // [1,1,128,128]
    (void)in_sizes; (void)n_in;

    const int smem_bytes = HH * PITCH * (int)sizeof(float);   // 66048 B >= 64KB labels
    cudaFuncSetAttribute(fused_hexloss_kernel,
                         cudaFuncAttributeMaxDynamicSharedMemorySize, smem_bytes);

    fused_hexloss_kernel<<<NB, NTHREADS, smem_bytes>>>(preds, templ, (float*)d_out, out_size);
}

// round 10
// speedup vs baseline: 22.8340x; 1.1324x over previous
#include <cuda_runtime.h>

#define HH 128
#define WW 128
#define NPIX (HH*WW)
#define NWORDS (NPIX/32)   // 512
#define NB 16
#define NTHREADS 1024
#define PITCH 129          // padded pitch for shared integral image

__device__ float g_sample[NB];
__device__ int   g_done = 0;   // self-resetting last-block ticket

// ---- lock-free union-find with atomicMin path-halving (monotone => race-safe) ----
__device__ __forceinline__ int find_root(int* lab, int a) {
    for (;;) {
        int p = lab[a];
        if (p == a) return a;
        int gp = lab[p];
        if (gp == p) return p;
        atomicMin(&lab[a], gp);
        a = gp;
    }
}
__device__ __forceinline__ void merge_px(int* lab, int a, int b) {
    for (;;) {
        a = find_root(lab, a);
        b = find_root(lab, b);
        if (a == b) return;
        int mn = min(a, b), mx = max(a, b);
        int old = atomicMin(&lab[mx], mn);
        if (old == mx) return;
        a = mn; b = old;
    }
}

// bit-sliced 1*p + 2*q + 1*r sum of three 32-lane bit vectors -> 3-bit lanes
#define SUM121(pp,qq,rr,s0,s1,s2) do { unsigned _c = (pp) & (rr); \
    s0 = (pp) ^ (rr); s1 = _c ^ (qq); s2 = _c & (qq); } while (0)

extern __shared__ char smem_raw[];

__global__ __launch_bounds__(NTHREADS)
void fused_hexloss_kernel(const float* __restrict__ preds,
                          const float* __restrict__ templ,
                          float* __restrict__ out, int out_size)
{
    // dynamic smem: phase A = padded float integral image (128x129 = 66048 B)
    //               phase B = int labels (64 KB), reused after all integral reads
    float* sS  = reinterpret_cast<float*>(smem_raw);
    int*   lab = reinterpret_cast<int*>(smem_raw);

    __shared__ unsigned mbits[NWORDS];        // 2 KB binary mask
    __shared__ int      s_last[NWORDS];       // last run-start per (row,word), or -1
    __shared__ float    s_segtot[NTHREADS];   // 4 KB segment totals (row, then col)
    __shared__ int      s_area[32], s_perim[32], s_ncomp[32];
    __shared__ double   s_wsum[32];

    const int b    = blockIdx.x;
    const int tid  = threadIdx.x;
    const int lane = tid & 31;
    const int warp = tid >> 5;                // 32 warps
    const unsigned FULL = 0xFFFFFFFFu;
    const float* p = preds + (size_t)b * NPIX;

    // chunk mapping: warps 0-15 own chunks + bookkeeping; warps 16-31 share wsum
    const int chunk = tid & 511;              // (row y, word w)
    const int upper = tid >> 9;
    const int y = chunk >> 2;
    const int w = chunk & 3;

    // ================= template row-local prefix (registers) + mask build =====
    const int rr = tid >> 3;                  // 0..127 row
    const int ss = tid & 7;                   // 0..7 16-col segment
    float v[16];
    {
        const float4* t4 = reinterpret_cast<const float4*>(templ + rr * 128 + ss * 16);
        float4 a0 = t4[0], a1 = t4[1], a2 = t4[2], a3 = t4[3];
        v[0]=a0.x; v[1]=a0.y; v[2]=a0.z; v[3]=a0.w;
        v[4]=a1.x; v[5]=a1.y; v[6]=a1.z; v[7]=a1.w;
        v[8]=a2.x; v[9]=a2.y; v[10]=a2.z; v[11]=a2.w;
        v[12]=a3.x; v[13]=a3.y; v[14]=a3.z; v[15]=a3.w;
    }
    // mask bits (independent global stream, overlaps template loads)
    for (int w0 = warp; w0 < NWORDS; w0 += 32) {
        float pv = p[w0 * 32 + lane];
        unsigned word = __ballot_sync(FULL, pv > 0.5f);
        if (lane == 0) mbits[w0] = word;
    }
    #pragma unroll
    for (int k = 1; k < 16; ++k) v[k] += v[k - 1];
    s_segtot[tid] = v[15];
    __syncthreads();   // bar1: mbits + row seg totals visible

    // ---- row offsets + store row-scanned values ----
    {
        float off = 0.0f;
        #pragma unroll
        for (int q = 0; q < 7; ++q) if (q < ss) off += s_segtot[(rr << 3) + q];
        float* dst = sS + rr * PITCH + ss * 16;
        #pragma unroll
        for (int k = 0; k < 16; ++k) dst[k] = v[k] + off;
    }

    // ---- Sobel / area / run-starts (lower half; needs only mbits) ----
    int area = 0, perim = 0;
    unsigned cur = 0, starts = 0;
    if (!upper) {
        cur = mbits[chunk];
        const unsigned prevw = (w > 0) ? mbits[y * 4 + w - 1] : 0u;
        const unsigned nextw = (w < 3) ? mbits[y * 4 + w + 1] : 0u;

        unsigned long long Ac = ((unsigned long long)cur << 1) | (prevw >> 31)
                              | ((unsigned long long)(nextw & 1u) << 33);
        unsigned long long Aa = 0ULL, Ab = 0ULL;
        if (y > 0) {
            unsigned c0 = mbits[(y - 1) * 4 + w];
            unsigned p0 = (w > 0) ? mbits[(y - 1) * 4 + w - 1] : 0u;
            unsigned n0 = (w < 3) ? mbits[(y - 1) * 4 + w + 1] : 0u;
            Aa = ((unsigned long long)c0 << 1) | (p0 >> 31) | ((unsigned long long)(n0 & 1u) << 33);
        }
        if (y < 127) {
            unsigned c0 = mbits[(y + 1) * 4 + w];
            unsigned p0 = (w > 0) ? mbits[(y + 1) * 4 + w - 1] : 0u;
            unsigned n0 = (w < 3) ? mbits[(y + 1) * 4 + w + 1] : 0u;
            Ab = ((unsigned long long)c0 << 1) | (p0 >> 31) | ((unsigned long long)(n0 & 1u) << 33);
        }
        unsigned aL = (unsigned)Aa, aC = (unsigned)(Aa >> 1), aR = (unsigned)(Aa >> 2);
        unsigned cL = (unsigned)Ac,                            cR = (unsigned)(Ac >> 2);
        unsigned bL = (unsigned)Ab, bC = (unsigned)(Ab >> 1), bR = (unsigned)(Ab >> 2);

        unsigned L0,L1,L2, R0,R1,R2, T0,T1,T2, B0,B1,B2;
        SUM121(aL, cL, bL, L0, L1, L2);
        SUM121(aR, cR, bR, R0, R1, R2);
        SUM121(aL, aC, aR, T0, T1, T2);
        SUM121(bL, bC, bR, B0, B1, B2);
        unsigned eqx = ~((L0 ^ R0) | (L1 ^ R1) | (L2 ^ R2));
        unsigned eqy = ~((T0 ^ B0) | (T1 ^ B1) | (T2 ^ B2));
        perim = __popc(~(eqx & eqy));
        area  = __popc(cur);

        starts = cur & ~((cur << 1) | (prevw >> 31));
        s_last[chunk] = starts ? (w * 32 + 31 - __clz(starts)) : -1;
    } else {
        cur = mbits[chunk];
    }
    __syncthreads();   // bar2: row-scanned sS complete

    // ================= column-local prefix (registers) ========================
    const int cc = rr;                        // 0..127 column
    float u[16];
    {
        #pragma unroll
        for (int k = 0; k < 16; ++k) u[k] = sS[(ss * 16 + k) * PITCH + cc];
        #pragma unroll
        for (int k = 1; k < 16; ++k) u[k] += u[k - 1];
        s_segtot[tid] = u[15];
    }
    __syncthreads();   // bar3: col seg totals visible, all row-stage reads done

    {
        float off = 0.0f;
        #pragma unroll
        for (int q = 0; q < 7; ++q) if (q < ss) off += s_segtot[(cc << 3) + q];
        #pragma unroll
        for (int k = 0; k < 16; ++k) sS[(ss * 16 + k) * PITCH + cc] = u[k] + off;
    }
    __syncthreads();   // bar4: integral image final

    // ================= template weighted sum over set pixels ==================
    // lower half takes even bits, upper half odd bits of the same chunk word
    float wsumf = 0.0f;
    {
        unsigned m = cur & (upper ? 0xAAAAAAAAu : 0x55555555u);
        const int y1 = min(HH - 1, y + 63);
        const int rbase1 = y1 * PITCH;
        const int rbase0 = (y > 64) ? (y - 65) * PITCH : -1;
        while (m) {
            int j = __ffs(m) - 1; m &= m - 1;
            int x  = w * 32 + j;
            int x1 = min(WW - 1, x + 63);
            float s = sS[rbase1 + x1];
            if (rbase0 >= 0) s -= sS[rbase0 + x1];
            if (x > 64) {
                s -= sS[rbase1 + (x - 65)];
                if (rbase0 >= 0) s += sS[rbase0 + (x - 65)];
            }
            wsumf += s;
        }
    }
    __syncthreads();   // bar5: all sS reads done -> reuse smem as labels

    // ================= labels init: run-start index per pixel =================
    if (!upper) {
        int carry = -1;
        for (int ww = w - 1; ww >= 0 && carry < 0; --ww) carry = s_last[y * 4 + ww];
        unsigned m = cur;
        const int rowbase = y * 128;
        while (m) {
            int j = __ffs(m) - 1; m &= m - 1;
            unsigned below = (j == 31) ? 0xFFFFFFFFu : ((2u << j) - 1u);
            unsigned sj = starts & below;
            int rs = sj ? (w * 32 + 31 - __clz(sj)) : carry;
            lab[rowbase + w * 32 + j] = rowbase + rs;
        }
    }
    __syncthreads();   // bar6: labels initialized

    // ---- vertical unions: one merge per overlap segment between adjacent rows ----
    if (tid < 508) {
        int r  = tid >> 2;
        int ww = tid & 3;
        unsigned ov = mbits[r * 4 + ww] & mbits[(r + 1) * 4 + ww];
        if (ov) {
            unsigned pov = (ww > 0) ? (mbits[r * 4 + ww - 1] & mbits[(r + 1) * 4 + ww - 1]) : 0u;
            unsigned ssg = ov & ~((ov << 1) | (pov >> 31));
            while (ssg) {
                int j = __ffs(ssg) - 1; ssg &= ssg - 1;
                int x = ww * 32 + j;
                merge_px(lab, lab[r * 128 + x], lab[(r + 1) * 128 + x]);
            }
        }
    }
    __syncthreads();   // bar7: union-find complete

    // ---- component count: run starts that remained roots ----
    int ncomp = 0;
    if (!upper) {
        unsigned st = starts;
        const int base = y * 128 + w * 32;
        while (st) {
            int j = __ffs(st) - 1; st &= st - 1;
            int i = base + j;
            if (lab[i] == i) ncomp++;
        }
    }

    // ---- block reduction (32 warps) ----
    double wsum = (double)wsumf;
    #pragma unroll
    for (int o = 16; o > 0; o >>= 1) {
        area  += __shfl_down_sync(FULL, area,  o);
        perim += __shfl_down_sync(FULL, perim, o);
        ncomp += __shfl_down_sync(FULL, ncomp, o);
        wsum  += __shfl_down_sync(FULL, wsum,  o);
    }
    if (lane == 0) { s_area[warp] = area; s_perim[warp] = perim; s_ncomp[warp] = ncomp; s_wsum[warp] = wsum; }
    __syncthreads();

    if (tid == 0) {
        int A = 0, P = 0, C = 0; double WS = 0.0;
        #pragma unroll
        for (int ww = 0; ww < 32; ++ww) { A += s_area[ww]; P += s_perim[ww]; C += s_ncomp[ww]; WS += s_wsum[ww]; }

        float fa = (float)A, fp = (float)P;
        float compact  = (fp * fp) / (fa + 1e-6f);
        float geometry = (A == 0) ? 0.0f : fabsf(compact - 4.51f);
        float multi    = (float)max(C - 1, 0);
        float tmpl     = 1.0f - (float)(WS / 16384.0);
        g_sample[b] = multi + geometry + tmpl;

        __threadfence();
        int ticket = atomicAdd(&g_done, 1);
        if (ticket == NB - 1) {
            double s = 0.0;
            #pragma unroll
            for (int i = 0; i < NB; ++i) s += (double)g_sample[i];
            float vv = (float)(s / (double)NB);   // WEIGHT = 1.0
            for (int i = 0; i < out_size; ++i) out[i] = vv;
            g_done = 0;   // reset for next graph replay
        }
    }
}

// ---------------------------------------------------------------------------
extern "C" void kernel_launch(void* const* d_in, const int* in_sizes, int n_in,
                              void* d_out, int out_size) {
    const float* preds = (const float*)d_in[0];   // [16,1,128,128]
    const float* templ = (const float*)d_in[1];   // [1,1,128,128]
    (void)in_sizes; (void)n_in;

    const int smem_bytes = HH * PITCH * (int)sizeof(float);   // 66048 B >= 64KB labels
    cudaFuncSetAttribute(fused_hexloss_kernel,
                         cudaFuncAttributeMaxDynamicSharedMemorySize, smem_bytes);

    fused_hexloss_kernel<<<NB, NTHREADS, smem_bytes>>>(preds, templ, (float*)d_out, out_size);
}

// round 11
// speedup vs baseline: 37.8767x; 1.6588x over previous
#include <cuda_runtime.h>

#define HH 128
#define WW 128
#define NPIX (HH*WW)
#define NWORDS (NPIX/32)   // 512
#define NB 16
#define NTHREADS 1024
#define PITCH 129

__device__ float g_geomloss[NB];
__device__ float g_comploss[NB];
__device__ int   g_done = 0;   // self-resetting ticket (counts to 32)

// ---- lock-free union-find with atomicMin path-halving (monotone => race-safe) ----
__device__ __forceinline__ int find_root(int* lab, int a) {
    for (;;) {
        int p = lab[a];
        if (p == a) return a;
        int gp = lab[p];
        if (gp == p) return p;
        atomicMin(&lab[a], gp);
        a = gp;
    }
}
__device__ __forceinline__ void merge_px(int* lab, int a, int b) {
    for (;;) {
        a = find_root(lab, a);
        b = find_root(lab, b);
        if (a == b) return;
        int mn = min(a, b), mx = max(a, b);
        int old = atomicMin(&lab[mx], mn);
        if (old == mx) return;
        a = mn; b = old;
    }
}

#define SUM121(pp,qq,rr,s0,s1,s2) do { unsigned _c = (pp) & (rr); \
    s0 = (pp) ^ (rr); s1 = _c ^ (qq); s2 = _c & (qq); } while (0)

extern __shared__ char smem_raw[];

__global__ __launch_bounds__(NTHREADS)
void fused_hexloss_kernel(const float* __restrict__ preds,
                          const float* __restrict__ templ,
                          float* __restrict__ out, int out_size)
{
    float* sS  = reinterpret_cast<float*>(smem_raw);   // geometry: integral image
    int*   lab = reinterpret_cast<int*>(smem_raw);     // CCL: labels

    __shared__ unsigned mbits[NWORDS];       // 2 KB
    __shared__ int      s_last[NWORDS];      // CCL only
    __shared__ float    s_segtot[NTHREADS];  // geometry scans
    __shared__ int      s_i0[32], s_i1[32];
    __shared__ double   s_d0[32];

    const int role = blockIdx.x >> 4;        // 0 = geometry, 1 = CCL
    const int img  = blockIdx.x & 15;
    const int tid  = threadIdx.x;
    const int lane = tid & 31;
    const int warp = tid >> 5;
    const unsigned FULL = 0xFFFFFFFFu;
    const float* p = preds + (size_t)img * NPIX;

    // ---- mask bits (both roles) ----
    for (int w0 = warp; w0 < NWORDS; w0 += 32) {
        float pv = p[w0 * 32 + lane];
        unsigned word = __ballot_sync(FULL, pv > 0.5f);
        if (lane == 0) mbits[w0] = word;
    }

    if (role == 0) {
        // =============== GEOMETRY BLOCK: integral + sobel + wsum ===============
        const int rr = tid >> 3;             // row 0..127
        const int ss = tid & 7;              // 16-col segment
        float v[16];
        {
            const float4* t4 = reinterpret_cast<const float4*>(templ + rr * 128 + ss * 16);
            float4 a0 = t4[0], a1 = t4[1], a2 = t4[2], a3 = t4[3];
            v[0]=a0.x; v[1]=a0.y; v[2]=a0.z; v[3]=a0.w;
            v[4]=a1.x; v[5]=a1.y; v[6]=a1.z; v[7]=a1.w;
            v[8]=a2.x; v[9]=a2.y; v[10]=a2.z; v[11]=a2.w;
            v[12]=a3.x; v[13]=a3.y; v[14]=a3.z; v[15]=a3.w;
        }
        #pragma unroll
        for (int k = 1; k < 16; ++k) v[k] += v[k - 1];
        s_segtot[ss * 128 + rr] = v[15];     // transposed: offset reads broadcast
        __syncthreads();                     // bar1: mbits + row seg totals

        {
            float off = 0.0f;
            #pragma unroll
            for (int q = 0; q < 7; ++q) if (q < ss) off += s_segtot[q * 128 + rr];
            float* dst = sS + rr * PITCH + ss * 16;
            #pragma unroll
            for (int k = 0; k < 16; ++k) dst[k] = v[k] + off;
        }

        // sobel / area / perim on lower 512 (pure ALU, overlaps)
        const int chunk = tid & 511;
        const int upper = tid >> 9;
        const int y = chunk >> 2, w = chunk & 3;
        const unsigned cur = mbits[chunk];
        int area = 0, perim = 0;
        if (!upper) {
            const unsigned prevw = (w > 0) ? mbits[y * 4 + w - 1] : 0u;
            const unsigned nextw = (w < 3) ? mbits[y * 4 + w + 1] : 0u;
            unsigned long long Ac = ((unsigned long long)cur << 1) | (prevw >> 31)
                                  | ((unsigned long long)(nextw & 1u) << 33);
            unsigned long long Aa = 0ULL, Ab = 0ULL;
            if (y > 0) {
                unsigned c0 = mbits[(y-1)*4+w];
                unsigned p0 = (w > 0) ? mbits[(y-1)*4+w-1] : 0u;
                unsigned n0 = (w < 3) ? mbits[(y-1)*4+w+1] : 0u;
                Aa = ((unsigned long long)c0 << 1) | (p0 >> 31) | ((unsigned long long)(n0 & 1u) << 33);
            }
            if (y < 127) {
                unsigned c0 = mbits[(y+1)*4+w];
                unsigned p0 = (w > 0) ? mbits[(y+1)*4+w-1] : 0u;
                unsigned n0 = (w < 3) ? mbits[(y+1)*4+w+1] : 0u;
                Ab = ((unsigned long long)c0 << 1) | (p0 >> 31) | ((unsigned long long)(n0 & 1u) << 33);
            }
            unsigned aL=(unsigned)Aa, aC=(unsigned)(Aa>>1), aR=(unsigned)(Aa>>2);
            unsigned cL=(unsigned)Ac,                       cR=(unsigned)(Ac>>2);
            unsigned bL=(unsigned)Ab, bC=(unsigned)(Ab>>1), bR=(unsigned)(Ab>>2);
            unsigned L0,L1,L2,R0,R1,R2,T0,T1,T2,B0,B1,B2;
            SUM121(aL,cL,bL,L0,L1,L2); SUM121(aR,cR,bR,R0,R1,R2);
            SUM121(aL,aC,aR,T0,T1,T2); SUM121(bL,bC,bR,B0,B1,B2);
            unsigned eqx = ~((L0^R0)|(L1^R1)|(L2^R2));
            unsigned eqy = ~((T0^B0)|(T1^B1)|(T2^B2));
            perim = __popc(~(eqx & eqy));
            area  = __popc(cur);
        }
        __syncthreads();                     // bar2: row-scanned sS complete

        // column scan: thread <-> (column cc, row segment sg) => conflict-free
        const int cc = tid & 127;
        const int sg = tid >> 7;
        float u[16];
        #pragma unroll
        for (int k = 0; k < 16; ++k) u[k] = sS[(sg * 16 + k) * PITCH + cc];
        #pragma unroll
        for (int k = 1; k < 16; ++k) u[k] += u[k - 1];
        s_segtot[sg * 128 + cc] = u[15];
        __syncthreads();                     // bar3

        {
            float off = 0.0f;
            #pragma unroll
            for (int q = 0; q < 7; ++q) if (q < sg) off += s_segtot[q * 128 + cc];
            #pragma unroll
            for (int k = 0; k < 16; ++k) sS[(sg * 16 + k) * PITCH + cc] = u[k] + off;
        }
        __syncthreads();                     // bar4: integral final

        // wsum: even/odd bit split across the two half-blocks
        float wsumf = 0.0f;
        {
            unsigned m = cur & (upper ? 0xAAAAAAAAu : 0x55555555u);
            const int y1 = min(HH - 1, y + 63);
            const int rbase1 = y1 * PITCH;
            const int rbase0 = (y > 64) ? (y - 65) * PITCH : -1;
            while (m) {
                int j = __ffs(m) - 1; m &= m - 1;
                int x  = w * 32 + j;
                int x1 = min(WW - 1, x + 63);
                float s = sS[rbase1 + x1];
                if (rbase0 >= 0) s -= sS[rbase0 + x1];
                if (x > 64) {
                    s -= sS[rbase1 + (x - 65)];
                    if (rbase0 >= 0) s += sS[rbase0 + (x - 65)];
                }
                wsumf += s;
            }
        }

        // reduce area/perim/wsum
        double wsum = (double)wsumf;
        #pragma unroll
        for (int o = 16; o > 0; o >>= 1) {
            area  += __shfl_down_sync(FULL, area,  o);
            perim += __shfl_down_sync(FULL, perim, o);
            wsum  += __shfl_down_sync(FULL, wsum,  o);
        }
        if (lane == 0) { s_i0[warp] = area; s_i1[warp] = perim; s_d0[warp] = wsum; }
        __syncthreads();
        if (tid == 0) {
            int A = 0, P = 0; double WS = 0.0;
            #pragma unroll
            for (int q = 0; q < 32; ++q) { A += s_i0[q]; P += s_i1[q]; WS += s_d0[q]; }
            float fa = (float)A, fp = (float)P;
            float compact  = (fp * fp) / (fa + 1e-6f);
            float geometry = (A == 0) ? 0.0f : fabsf(compact - 4.51f);
            float tmpl     = 1.0f - (float)(WS / 16384.0);
            g_geomloss[img] = geometry + tmpl;
        }
    } else {
        // =============== CCL BLOCK: labels + union-find + count ===============
        __syncthreads();                     // bar1: mbits visible

        // thread pair <-> chunk: chunk2 = tid>>1, half = tid&1 (16-bit halves)
        const int chunk2 = tid >> 1;
        const int half   = tid & 1;
        const int y = chunk2 >> 2, w = chunk2 & 3;
        const unsigned cur   = mbits[chunk2];
        const unsigned prevw = (w > 0) ? mbits[y * 4 + w - 1] : 0u;
        const unsigned starts = cur & ~((cur << 1) | (prevw >> 31));
        const unsigned halfmask = half ? 0xFFFF0000u : 0x0000FFFFu;
        if (!half) s_last[chunk2] = starts ? (w * 32 + 31 - __clz(starts)) : -1;
        __syncthreads();                     // bar2: s_last visible

        // labels init (set pixels in this half-word)
        {
            int carry = -1;
            for (int ww = w - 1; ww >= 0 && carry < 0; --ww) carry = s_last[y * 4 + ww];
            unsigned m = cur & halfmask;
            const int rowbase = y * 128;
            while (m) {
                int j = __ffs(m) - 1; m &= m - 1;
                unsigned below = (j == 31) ? 0xFFFFFFFFu : ((2u << j) - 1u);
                unsigned sj = starts & below;
                int rs = sj ? (w * 32 + 31 - __clz(sj)) : carry;
                lab[rowbase + w * 32 + j] = rowbase + rs;
            }
        }
        __syncthreads();                     // bar3: labels initialized

        // vertical unions: thread <-> (row r, word ww, half) => 8 threads/row
        {
            const int r   = tid >> 3;        // 0..127
            const int sub = tid & 7;
            const int ww  = sub >> 1;
            const unsigned hm = (sub & 1) ? 0xFFFF0000u : 0x0000FFFFu;
            if (r < 127) {
                unsigned ov = mbits[r * 4 + ww] & mbits[(r + 1) * 4 + ww];
                if (ov & hm) {
                    unsigned pov = (ww > 0) ? (mbits[r * 4 + ww - 1] & mbits[(r + 1) * 4 + ww - 1]) : 0u;
                    unsigned ssg = (ov & ~((ov << 1) | (pov >> 31))) & hm;
                    while (ssg) {
                        int j = __ffs(ssg) - 1; ssg &= ssg - 1;
                        int x = ww * 32 + j;
                        merge_px(lab, lab[r * 128 + x], lab[(r + 1) * 128 + x]);
                    }
                }
            }
        }
        __syncthreads();                     // bar4: UF complete

        // count roots among run starts (half-word split)
        int ncomp = 0;
        {
            unsigned st = starts & halfmask;
            const int base = y * 128 + w * 32;
            while (st) {
                int j = __ffs(st) - 1; st &= st - 1;
                int i = base + j;
                if (lab[i] == i) ncomp++;
            }
        }
        #pragma unroll
        for (int o = 16; o > 0; o >>= 1)
            ncomp += __shfl_down_sync(FULL, ncomp, o);
        if (lane == 0) s_i0[warp] = ncomp;
        __syncthreads();
        if (tid == 0) {
            int C = 0;
            #pragma unroll
            for (int q = 0; q < 32; ++q) C += s_i0[q];
            g_comploss[img] = (float)max(C - 1, 0);
        }
    }

    // =============== last-block finalize (deterministic fixed order) ===============
    if (tid == 0) {
        __threadfence();
        int ticket = atomicAdd(&g_done, 1);
        if (ticket == 2 * NB - 1) {
            double s = 0.0;
            #pragma unroll
            for (int i = 0; i < NB; ++i) s += (double)g_geomloss[i] + (double)g_comploss[i];
            float vv = (float)(s / (double)NB);   // WEIGHT = 1.0
            for (int i = 0; i < out_size; ++i) out[i] = vv;
            g_done = 0;
        }
    }
}

// ---------------------------------------------------------------------------
extern "C" void kernel_launch(void* const* d_in, const int* in_sizes, int n_in,
                              void* d_out, int out_size) {
    const float* preds = (const float*)d_in[0];   // [16,1,128,128]
    const float* templ = (const float*)d_in[1];   // [1,1,128,128]
    (void)in_sizes; (void)n_in;

    const int smem_bytes = HH * PITCH * (int)sizeof(float);   // 66048 B >= 64KB labels
    cudaFuncSetAttribute(fused_hexloss_kernel,
                         cudaFuncAttributeMaxDynamicSharedMemorySize, smem_bytes);

    fused_hexloss_kernel<<<2 * NB, NTHREADS, smem_bytes>>>(preds, templ, (float*)d_out, out_size);
}